// round 10
// baseline (speedup 1.0000x reference)
#include <cuda_runtime.h>
#include <cuda_fp16.h>
#include <cstdint>

typedef unsigned long long u64;
typedef unsigned int u32;
typedef unsigned short u16;

// Problem geometry
#define CB_K 512
#define CB_C 64
#define HW   4096
#define NPLANES 128
#define N_PIX 524288
#define Q_ELEMS 33554432
#define OFF_IDX  Q_ELEMS
#define OFF_LOSS (OFF_IDX + N_PIX)
#define OFF_ENT  (OFF_LOSS + 1)

#define THREADS 256
#define PIX_PER_CTA 512
#define NBLOCKS 1024
#define ESR 68                        // es row stride (floats); 272B = 16B-aligned rows

// smem byte offsets
#define SB_ES    0                    // es[k][c] fp32: 512*68*4 = 139264
#define SB_EH    139264               // eh[c*256+kp] half2 {e_2kp, e_2kp+1}: 65536
#define SB_EE    204800               // E_k fp32: 2048
#define SB_HIST  206848               // 2048
#define SB_CAND  208896               // 512 px * 16 u16 = 16384
#define SB_LANE  225280               // 4 f32
#define SB_EMAXR 225296               // 4 int (per-chain Emax)
#define SMEM_TOTAL 225344

__device__ double g_lane[4];
__device__ int    g_counts[CB_K];

__global__ void vq_zero() {
    int t = threadIdx.x;
    if (t < CB_K) g_counts[t] = 0;
    if (t < 4)    g_lane[t] = 0.0;
}

__device__ __forceinline__ u32 pack_h2(float lo, float hi){
    u32 h; asm("cvt.rn.f16x2.f32 %0, %1, %2;" : "=r"(h) : "f"(hi), "f"(lo));
    return h;
}
#define HFMA2(acc, a, b) asm("fma.rn.f16x2 %0, %1, %2, %0;" : "+r"(acc) : "r"(a), "r"(b))
__device__ __forceinline__ u32 hadd2(u32 a, u32 b){
    u32 d; asm("add.rn.f16x2 %0, %1, %2;" : "=r"(d) : "r"(a), "r"(b));
    return d;
}

__global__ void __launch_bounds__(THREADS, 1)
vq_main(const float* __restrict__ x, const float* __restrict__ cb, float* __restrict__ out) {
    extern __shared__ char smem[];
    float* es   = (float*)(smem + SB_ES);
    u32*   eh   = (u32*)(smem + SB_EH);
    float* ee   = (float*)(smem + SB_EE);
    int*   hist = (int*)(smem + SB_HIST);
    u16*   cand = (u16*)(smem + SB_CAND);
    float* lane_sum = (float*)(smem + SB_LANE);
    int*   emaxr    = (int*)(smem + SB_EMAXR);

    const int tid = threadIdx.x;
    const int plane = blockIdx.x >> 3;
    const int j0 = ((blockIdx.x & 7) * PIX_PER_CTA) + 2 * tid;
    const float* xp = x + (size_t)plane * (CB_C * HW) + j0;

    // ---- stage codebook fp32 (coalesced LDG.128 -> aligned STS.128) ----
    for (int i = tid; i < CB_K * 16; i += THREADS) {
        int k = i >> 4, c4 = i & 15;
        *(float4*)(es + k * ESR + 4 * c4) = *(const float4*)(cb + k * CB_C + 4 * c4);
    }
    for (int k = tid; k < CB_K; k += THREADS) hist[k] = 0;
    if (tid < 4) { lane_sum[tid] = 0.f; emaxr[tid] = 0; }
    __syncthreads();

    // ---- fp16 codebook (lo = even code, hi = odd code) ----
    for (int i = tid; i < CB_C * 256; i += THREADS) {
        int kp = i & 255, c = i >> 8;
        eh[c * 256 + kp] = pack_h2(es[(2 * kp) * ESR + c], es[(2 * kp + 1) * ESR + c]);
    }
    // ---- E_k exact (sequential fma ascending c) + per-chain Emax ----
    for (int k = tid; k < CB_K; k += THREADS) {
        const float* er = es + k * ESR;
        float s = 0.f, s0 = 0.f, s1 = 0.f, s2 = 0.f, s3 = 0.f;
        #pragma unroll
        for (int c4 = 0; c4 < 16; ++c4) {
            float4 e = *(const float4*)(er + 4 * c4);
            s = __fmaf_rn(e.x, e.x, s); s = __fmaf_rn(e.y, e.y, s);
            s = __fmaf_rn(e.z, e.z, s); s = __fmaf_rn(e.w, e.w, s);
            s0 = __fmaf_rn(e.x, e.x, s0); s1 = __fmaf_rn(e.y, e.y, s1);
            s2 = __fmaf_rn(e.z, e.z, s2); s3 = __fmaf_rn(e.w, e.w, s3);
        }
        ee[k] = s;
        atomicMax(&emaxr[0], __float_as_int(s0));
        atomicMax(&emaxr[1], __float_as_int(s1));
        atomicMax(&emaxr[2], __float_as_int(s2));
        atomicMax(&emaxr[3], __float_as_int(s3));
    }

    // ---- x pass: S (exact chain), per-chain S_r, fp16 pack (f regs then die) ----
    float S0 = 0.f, S1 = 0.f;
    float S0r[4] = {0,0,0,0}, S1r[4] = {0,0,0,0};
    u32 fh[CB_C];
    #pragma unroll
    for (int c = 0; c < CB_C; ++c) {
        float2 v = *(const float2*)(xp + (size_t)c * HW);
        S0 = __fmaf_rn(v.x, v.x, S0);
        S1 = __fmaf_rn(v.y, v.y, S1);
        S0r[c & 3] = __fmaf_rn(v.x, v.x, S0r[c & 3]);
        S1r[c & 3] = __fmaf_rn(v.y, v.y, S1r[c & 3]);
        fh[c] = pack_h2(v.x, v.y);        // lo = px0, hi = px1
    }
    __syncthreads();

    // ---- sound fp16 window: W = 0.025 * sum_r sqrt(S_r * Emax_r) + 1e-4 ----
    float tw0, tw1;
    {
        float p0 = 0.f, p1 = 0.f;
        #pragma unroll
        for (int r = 0; r < 4; ++r) {
            float Em = __int_as_float(emaxr[r]);
            p0 += __fsqrt_rn(S0r[r] * Em);
            p1 += __fsqrt_rn(S1r[r] * Em);
        }
        tw0 = __fmaf_rn(0.05f, p0, 2e-4f);   // 2*W
        tw1 = __fmaf_rn(0.05f, p1, 2e-4f);
    }

    u16* cb0 = cand + (2 * tid) * 16;
    u16* cb1 = cb0 + 16;
    int cnt0 = 0, cnt1 = 0;
    float mr0 = 3.4e38f, mr1 = 3.4e38f;

    // ---- HFMA2 screen: 64 tiles x 8 codes; 4 interleaved fp16 chains (c mod 4) ----
    unsigned ehb = (unsigned)__cvta_generic_to_shared(eh);
    #pragma unroll 1
    for (int kt = 0; kt < 64; ++kt) {
        u32 a0[16], a1[16];
        #pragma unroll
        for (int i = 0; i < 16; ++i) { a0[i] = 0u; a1[i] = 0u; }
        unsigned eaddr = ehb + (unsigned)(kt * 16);
        #pragma unroll
        for (int c = 0; c < CB_C; ++c) {
            u32 w0, w1, w2, w3;
            asm volatile("ld.shared.v4.u32 {%0,%1,%2,%3}, [%4];"
                : "=r"(w0), "=r"(w1), "=r"(w2), "=r"(w3)
                : "r"(eaddr + (unsigned)(c * 1024)));
            u32 b0, b1;
            asm("prmt.b32 %0, %1, %1, 0x1010;" : "=r"(b0) : "r"(fh[c]));
            asm("prmt.b32 %0, %1, %1, 0x3232;" : "=r"(b1) : "r"(fh[c]));
            const int r4 = (c & 3) * 4;
            HFMA2(a0[r4 + 0], w0, b0); HFMA2(a0[r4 + 1], w1, b0);
            HFMA2(a0[r4 + 2], w2, b0); HFMA2(a0[r4 + 3], w3, b0);
            HFMA2(a1[r4 + 0], w0, b1); HFMA2(a1[r4 + 1], w1, b1);
            HFMA2(a1[r4 + 2], w2, b1); HFMA2(a1[r4 + 3], w3, b1);
        }
        // merge 4 chains, unpack, distances, two-pass flag
        float Ev[8];
        {
            float4 Ea = *(const float4*)(ee + kt * 8);
            float4 Eb = *(const float4*)(ee + kt * 8 + 4);
            Ev[0]=Ea.x; Ev[1]=Ea.y; Ev[2]=Ea.z; Ev[3]=Ea.w;
            Ev[4]=Eb.x; Ev[5]=Eb.y; Ev[6]=Eb.z; Ev[7]=Eb.w;
        }
        float d0[8], d1[8];
        #pragma unroll
        for (int q = 0; q < 4; ++q) {
            u32 m0 = hadd2(hadd2(a0[q], a0[4 + q]), hadd2(a0[8 + q], a0[12 + q]));
            u32 m1 = hadd2(hadd2(a1[q], a1[4 + q]), hadd2(a1[8 + q], a1[12 + q]));
            float2 Da = __half22float2(*reinterpret_cast<__half2*>(&m0));
            float2 Db = __half22float2(*reinterpret_cast<__half2*>(&m1));
            d0[2*q]   = __fmaf_rn(-2.f, Da.x, S0 + Ev[2*q]);
            d0[2*q+1] = __fmaf_rn(-2.f, Da.y, S0 + Ev[2*q+1]);
            d1[2*q]   = __fmaf_rn(-2.f, Db.x, S1 + Ev[2*q]);
            d1[2*q+1] = __fmaf_rn(-2.f, Db.y, S1 + Ev[2*q+1]);
        }
        float t0 = mr0, t1 = mr1;
        #pragma unroll
        for (int jq = 0; jq < 8; ++jq) { t0 = fminf(t0, d0[jq]); t1 = fminf(t1, d1[jq]); }
        const float thr0 = t0 + tw0, thr1 = t1 + tw1;
        #pragma unroll
        for (int jq = 0; jq < 8; ++jq) {
            if (d0[jq] <= thr0) { if (cnt0 < 16) cb0[cnt0] = (u16)(kt * 8 + jq); cnt0++; }
            if (d1[jq] <= thr1) { if (cnt1 < 16) cb1[cnt1] = (u16)(kt * 8 + jq); cnt1++; }
        }
        mr0 = t0; mr1 = t1;
    }

    // ---- reload f (fp32, coalesced; same gmem values) ----
    float2 f[CB_C];
    #pragma unroll
    for (int c = 0; c < CB_C; ++c) f[c] = *(const float2*)(xp + (size_t)c * HW);

    // ---- exact verification (reference two-rounding chain), ascending k ----
    float bd0 = 3.4e38f, bd1 = 3.4e38f;
    int bk0 = 0, bk1 = 0;
    {
        int n0 = (cnt0 <= 16) ? cnt0 : CB_K;
        for (int i = 0; i < n0; ++i) {
            int k = (cnt0 <= 16) ? (int)cb0[i] : i;
            const float* er = es + k * ESR;
            float D = 0.f;
            #pragma unroll
            for (int c4 = 0; c4 < 16; ++c4) {
                float4 e = *(const float4*)(er + 4 * c4);
                D = __fmaf_rn(f[4*c4+0].x, e.x, D);
                D = __fmaf_rn(f[4*c4+1].x, e.y, D);
                D = __fmaf_rn(f[4*c4+2].x, e.z, D);
                D = __fmaf_rn(f[4*c4+3].x, e.w, D);
            }
            float d = __fadd_rn(__fmaf_rn(-2.f, D, S0), ee[k]);
            if (d < bd0) { bd0 = d; bk0 = k; }
        }
        int n1 = (cnt1 <= 16) ? cnt1 : CB_K;
        for (int i = 0; i < n1; ++i) {
            int k = (cnt1 <= 16) ? (int)cb1[i] : i;
            const float* er = es + k * ESR;
            float D = 0.f;
            #pragma unroll
            for (int c4 = 0; c4 < 16; ++c4) {
                float4 e = *(const float4*)(er + 4 * c4);
                D = __fmaf_rn(f[4*c4+0].y, e.x, D);
                D = __fmaf_rn(f[4*c4+1].y, e.y, D);
                D = __fmaf_rn(f[4*c4+2].y, e.z, D);
                D = __fmaf_rn(f[4*c4+3].y, e.w, D);
            }
            float d = __fadd_rn(__fmaf_rn(-2.f, D, S1), ee[k]);
            if (d < bd1) { bd1 = d; bk1 = k; }
        }
    }

    // ---- outputs + losses (R3-validated machinery) ----
    atomicAdd(&hist[bk0], 1);
    atomicAdd(&hist[bk1], 1);
    {
        size_t pix = (size_t)plane * HW + j0;
        *(float2*)(out + OFF_IDX + pix) = make_float2((float)bk0, (float)bk1);
    }

    const bool quant = (plane >= 2);
    float scaleQ = 1.f, invQ = 1.f;
    if (quant) {
        int lg = 31 - __clz(plane);
        int kq = 7 - lg;
        scaleQ = (float)(1 << kq);
        invQ   = 1.f / (float)(1 << kq);
    }
    float acc0 = 0.f, acc1 = 0.f;
    float* outq = out + (size_t)plane * (CB_C * HW) + j0;
    const float* q0r = es + bk0 * ESR;
    const float* q1r = es + bk1 * ESR;
    #pragma unroll
    for (int c = 0; c < CB_C; ++c) {
        float q0 = q0r[c], q1 = q1r[c];
        float da = __fsub_rn(q0, f[c].x);
        float db = __fsub_rn(q1, f[c].y);
        float v0 = __fmul_rn(da, da);
        float v1 = __fmul_rn(db, db);
        if (quant) {
            float m0 = __fsub_rn(__fmaf_rn(v0, scaleQ, 8388608.f), 8388608.f);
            float m1 = __fsub_rn(__fmaf_rn(v1, scaleQ, 8388608.f), 8388608.f);
            acc0 = __fmaf_rn(m0, invQ, acc0);
            acc1 = __fmaf_rn(m1, invQ, acc1);
        } else {
            acc0 = __fadd_rn(v0, acc0);
            acc1 = __fadd_rn(v1, acc1);
        }
        *(float2*)(outq + (size_t)c * HW) =
            make_float2(__fadd_rn(f[c].x, da), __fadd_rn(f[c].y, db));
    }
    atomicAdd(&lane_sum[j0 & 3], acc0);
    atomicAdd(&lane_sum[(j0 & 3) + 1], acc1);
    __syncthreads();
    if (tid < 4) atomicAdd(&g_lane[tid], (double)lane_sum[tid]);
    for (int k = tid; k < CB_K; k += THREADS) {
        int c = hist[k];
        if (c) atomicAdd(&g_counts[k], c);
    }
}

__global__ void vq_finalize(float* __restrict__ out) {
    __shared__ double red[CB_K];
    int t = threadIdx.x;
    int c = g_counts[t];
    double p = (double)c / (double)N_PIX;
    red[t] = (c > 0) ? (-p * log2(p)) : 0.0;
    __syncthreads();
    for (int o = CB_K / 2; o > 0; o >>= 1) {
        if (t < o) red[t] += red[t + o];
        __syncthreads();
    }
    if (t == 0) {
        out[OFF_ENT] = (float)red[0];
        float s0 = (float)g_lane[0], s1 = (float)g_lane[1];
        float s2 = (float)g_lane[2], s3 = (float)g_lane[3];
        float hs = __fadd_rn(__fadd_rn(s0, s1), __fadd_rn(s2, s3));
        float L  = hs * (1.f / 33554432.f);
        out[OFF_LOSS] = __fadd_rn(L, 0.25f * L);
    }
}

extern "C" void kernel_launch(void* const* d_in, const int* in_sizes, int n_in,
                              void* d_out, int out_size) {
    const float* x  = (const float*)d_in[0];
    const float* cb = (const float*)d_in[1];
    float* out = (float*)d_out;
    cudaFuncSetAttribute(vq_main, cudaFuncAttributeMaxDynamicSharedMemorySize, SMEM_TOTAL);
    vq_zero<<<1, CB_K>>>();
    vq_main<<<NBLOCKS, THREADS, SMEM_TOTAL>>>(x, cb, out);
    vq_finalize<<<1, CB_K>>>(out);
}

// round 11
// speedup vs baseline: 3.2223x; 3.2223x over previous
#include <cuda_runtime.h>
#include <cstdint>

// Problem geometry
#define CB_K 512
#define CB_C 64
#define HW   4096                     // 64*64 pixels per (b,t) plane
#define N_PIX  524288
#define Q_ELEMS 33554432
#define OFF_IDX  Q_ELEMS
#define OFF_LOSS (OFF_IDX + N_PIX)
#define OFF_ENT  (OFF_LOSS + 1)

// Persistent config: 148 CTAs (1/SM), 256 threads, equal pixel split
#define THREADS 256
#define NCTAS   148
#define ESTRIDE 516                   // padded floats per channel row of codebook
#define SMEM_FLOATS (CB_C * ESTRIDE)  // 33024 floats
#define SMEM_BYTES (SMEM_FLOATS*4 + CB_K*4 /*E*/ + CB_K*4 /*hist*/ + 4*4 /*lane_sum*/)

typedef unsigned long long u64;

__device__ double   g_lane[4] = {0.0, 0.0, 0.0, 0.0};
__device__ int      g_counts[CB_K] = {};
__device__ unsigned g_ticket = 0u;

__global__ void __launch_bounds__(THREADS, 1)
vq_main(const float* __restrict__ x, const float* __restrict__ cb, float* __restrict__ out) {
    extern __shared__ float smem[];
    float* es   = smem;                       // codebook transposed [c][k], stride 516
    float* ee   = smem + SMEM_FLOATS;         // E_k (fp32 sequential fma, reference chain)
    int*   hist = (int*)(ee + CB_K);          // per-CTA histogram (whole CTA lifetime)
    float* lane_sum = (float*)(hist + CB_K);  // per-CTA loss partials by (index mod 4)

    const int tid = threadIdx.x;

    // ---- one-time staging per CTA (persistent: amortized over ~7 tiles) ----
    for (int i = tid; i < CB_K * CB_C; i += THREADS) {
        int k = i >> 6, c = i & 63;
        es[c * ESTRIDE + k] = cb[i];
    }
    for (int k = tid; k < CB_K; k += THREADS) hist[k] = 0;
    if (tid < 4) lane_sum[tid] = 0.f;
    __syncthreads();
    for (int k = tid; k < CB_K; k += THREADS) {
        float s = 0.f;
        #pragma unroll
        for (int c = 0; c < CB_C; ++c) { float e = es[c * ESTRIDE + k]; s = __fmaf_rn(e, e, s); }
        ee[k] = s;
    }
    __syncthreads();

    unsigned sbase = (unsigned)__cvta_generic_to_shared(es);
    unsigned hbase = (unsigned)__cvta_generic_to_shared(ee);

    // ---- equal pixel-range split across 148 CTAs (even-aligned boundaries) ----
    const unsigned b = blockIdx.x;
    const unsigned pstart = 2u * ((b * 262144u) / 148u);
    const unsigned pend   = 2u * (((b + 1u) * 262144u) / 148u);

    for (unsigned p0 = pstart + 2u * (unsigned)tid; p0 < pend; p0 += 2u * THREADS) {
        const unsigned plane = p0 >> 12;
        const unsigned j0 = p0 & 4095u;
        const float* xp = x + (size_t)plane * (CB_C * HW) + j0;

        // two adjacent pixels per thread; all channels in registers (x read once)
        float2 f[CB_C];
        #pragma unroll
        for (int c = 0; c < CB_C; ++c) f[c] = *(const float2*)(xp + (size_t)c * HW);

        float Sa = 0.f, Sb = 0.f;
        #pragma unroll
        for (int c = 0; c < CB_C; ++c) {
            Sa = __fmaf_rn(f[c].x, f[c].x, Sa);
            Sb = __fmaf_rn(f[c].y, f[c].y, Sb);
        }

        float bestA = 3.4e38f, bestB = 3.4e38f;
        int biA = 0, biB = 0;

        // 64 tiles of 8 codes: packed-FFMA2 sequential-fma dot, then the reference
        // two-rounding chain: t = fl(S - 2D); d = fl(t + E_k); argmin ascending k.
        #pragma unroll 1
        for (int kt = 0; kt < CB_K / 8; ++kt) {
            u64 a[4] = {0,0,0,0}, bb[4] = {0,0,0,0};
            unsigned ebase = sbase + (unsigned)(kt * 32);
            #pragma unroll
            for (int c = 0; c < CB_C; ++c) {
                u64 e0, e1, e2, e3;
                unsigned ea = ebase + (unsigned)(c * (ESTRIDE * 4));
                asm volatile("ld.shared.v2.u64 {%0,%1}, [%2];"    : "=l"(e0), "=l"(e1) : "r"(ea));
                asm volatile("ld.shared.v2.u64 {%0,%1}, [%2+16];" : "=l"(e2), "=l"(e3) : "r"(ea));
                u64 fa, fb;
                asm("mov.b64 %0, {%1,%1};" : "=l"(fa) : "f"(f[c].x));
                asm("mov.b64 %0, {%1,%1};" : "=l"(fb) : "f"(f[c].y));
                asm("fma.rn.f32x2 %0, %1, %2, %0;" : "+l"(a[0])  : "l"(fa), "l"(e0));
                asm("fma.rn.f32x2 %0, %1, %2, %0;" : "+l"(a[1])  : "l"(fa), "l"(e1));
                asm("fma.rn.f32x2 %0, %1, %2, %0;" : "+l"(a[2])  : "l"(fa), "l"(e2));
                asm("fma.rn.f32x2 %0, %1, %2, %0;" : "+l"(a[3])  : "l"(fa), "l"(e3));
                asm("fma.rn.f32x2 %0, %1, %2, %0;" : "+l"(bb[0]) : "l"(fb), "l"(e0));
                asm("fma.rn.f32x2 %0, %1, %2, %0;" : "+l"(bb[1]) : "l"(fb), "l"(e1));
                asm("fma.rn.f32x2 %0, %1, %2, %0;" : "+l"(bb[2]) : "l"(fb), "l"(e2));
                asm("fma.rn.f32x2 %0, %1, %2, %0;" : "+l"(bb[3]) : "l"(fb), "l"(e3));
            }
            u64 h[4];
            {
                unsigned ha = hbase + (unsigned)(kt * 32);
                asm volatile("ld.shared.v2.u64 {%0,%1}, [%2];"    : "=l"(h[0]), "=l"(h[1]) : "r"(ha));
                asm volatile("ld.shared.v2.u64 {%0,%1}, [%2+16];" : "=l"(h[2]), "=l"(h[3]) : "r"(ha));
            }
            #pragma unroll
            for (int q = 0; q < 4; ++q) {
                float elo = __uint_as_float((unsigned)h[q]);
                float ehi = __uint_as_float((unsigned)(h[q] >> 32));
                float Dal = __uint_as_float((unsigned)a[q]);
                float Dah = __uint_as_float((unsigned)(a[q] >> 32));
                float Dbl = __uint_as_float((unsigned)bb[q]);
                float Dbh = __uint_as_float((unsigned)(bb[q] >> 32));
                float dAl = __fadd_rn(__fmaf_rn(-2.f, Dal, Sa), elo);
                float dAh = __fadd_rn(__fmaf_rn(-2.f, Dah, Sa), ehi);
                float dBl = __fadd_rn(__fmaf_rn(-2.f, Dbl, Sb), elo);
                float dBh = __fadd_rn(__fmaf_rn(-2.f, Dbh, Sb), ehi);
                int k0 = kt * 8 + 2 * q;
                if (dAl < bestA) { bestA = dAl; biA = k0;     }
                if (dAh < bestA) { bestA = dAh; biA = k0 + 1; }
                if (dBl < bestB) { bestB = dBl; biB = k0;     }
                if (dBh < bestB) { bestB = dBh; biB = k0 + 1; }
            }
        }

        atomicAdd(&hist[biA], 1);
        atomicAdd(&hist[biB], 1);

        // ---- loss (XLA NEON-vec4 emulation, validated) + ST output ----
        const bool quant = (plane >= 2);
        float scaleQ = 1.f, invQ = 1.f;
        if (quant) {
            int lg = 31 - __clz((int)plane);   // 1..6
            int kq = 7 - lg;                    // 6..1
            scaleQ = (float)(1 << kq);
            invQ   = 1.f / (float)(1 << kq);
        }
        float acc0 = 0.f, acc1 = 0.f;
        float* outq = out + (size_t)plane * (CB_C * HW) + j0;
        #pragma unroll
        for (int c = 0; c < CB_C; ++c) {
            float qa = es[c * ESTRIDE + biA];
            float qb = es[c * ESTRIDE + biB];
            float da = __fsub_rn(qa, f[c].x);
            float db = __fsub_rn(qb, f[c].y);
            float v0 = __fmul_rn(da, da);
            float v1 = __fmul_rn(db, db);
            if (quant) {
                float m0 = __fsub_rn(__fmaf_rn(v0, scaleQ, 8388608.f), 8388608.f);
                float m1 = __fsub_rn(__fmaf_rn(v1, scaleQ, 8388608.f), 8388608.f);
                acc0 = __fmaf_rn(m0, invQ, acc0);
                acc1 = __fmaf_rn(m1, invQ, acc1);
            } else {
                acc0 = __fadd_rn(v0, acc0);
                acc1 = __fadd_rn(v1, acc1);
            }
            *(float2*)(outq + (size_t)c * HW) =
                make_float2(__fadd_rn(f[c].x, da), __fadd_rn(f[c].y, db));
        }
        *(float2*)(out + OFF_IDX + p0) = make_float2((float)biA, (float)biB);

        // shared fp32 atomics: quantized values are multiples of 2^-6, CTA-lane
        // totals < 2^18 -> exact; planes 0-1 within existing noise budget.
        atomicAdd(&lane_sum[p0 & 3], acc0);
        atomicAdd(&lane_sum[(p0 & 3) + 1], acc1);
    }

    // ---- per-CTA flush ----
    __syncthreads();
    if (tid < 4) atomicAdd(&g_lane[tid], (double)lane_sum[tid]);
    for (int k = tid; k < CB_K; k += THREADS) {
        int cth = hist[k];
        if (cth) atomicAdd(&g_counts[k], cth);
    }

    // ---- last-CTA finalize + self-reset (graph-replay deterministic) ----
    __shared__ unsigned is_last;
    __threadfence();
    if (tid == 0) is_last = (atomicAdd(&g_ticket, 1u) == NCTAS - 1u) ? 1u : 0u;
    __syncthreads();
    if (is_last) {
        __threadfence();
        double e = 0.0;
        for (int k = tid; k < CB_K; k += THREADS) {
            int c = g_counts[k];
            if (c) { double p = (double)c / (double)N_PIX; e -= p * log2(p); }
            g_counts[k] = 0;
        }
        double* red = (double*)smem;   // es region dead; 16B-aligned
        red[tid] = e;
        __syncthreads();
        for (int o = THREADS / 2; o > 0; o >>= 1) {
            if (tid < o) red[tid] += red[tid + o];
            __syncthreads();
        }
        if (tid == 0) {
            out[OFF_ENT] = (float)red[0];
            // NEON faddp horizontal reduce: (s0+s1) + (s2+s3), all fp32.
            float s0 = (float)g_lane[0], s1 = (float)g_lane[1];
            float s2 = (float)g_lane[2], s3 = (float)g_lane[3];
            float hs = __fadd_rn(__fadd_rn(s0, s1), __fadd_rn(s2, s3));
            float L  = hs * (1.f / 33554432.f);
            out[OFF_LOSS] = __fadd_rn(L, 0.25f * L);
            g_lane[0] = 0.0; g_lane[1] = 0.0; g_lane[2] = 0.0; g_lane[3] = 0.0;
            g_ticket = 0u;
        }
    }
}

extern "C" void kernel_launch(void* const* d_in, const int* in_sizes, int n_in,
                              void* d_out, int out_size) {
    const float* x  = (const float*)d_in[0];
    const float* cb = (const float*)d_in[1];
    float* out = (float*)d_out;
    cudaFuncSetAttribute(vq_main, cudaFuncAttributeMaxDynamicSharedMemorySize, SMEM_BYTES);
    vq_main<<<NCTAS, THREADS, SMEM_BYTES>>>(x, cb, out);
}